// round 11
// baseline (speedup 1.0000x reference)
#include <cuda_runtime.h>
#include <cstdint>

#define SEQ   2048
#define D_IN  300
#define UDIM  150
#define ZDIM  600
#define H1    300
#define NSYN  4
#define TS    16

// ---------------- scratch (no cudaMalloc allowed) ----------------
__device__ float g_X[2][SEQ*ZDIM];     // x@Wk + b, per direction
__device__ float g_hidden[SEQ*H1];     // [hf | hb]
__device__ float g_out[SEQ*H1];        // hidden@W1 + b1
__device__ float g_wbuf[SEQ*H1];       // c2[s]*h_hat[s]

__device__ __forceinline__ uint32_t smem_u32(const void* p){
  uint32_t a;
  asm("{ .reg .u64 t; cvta.to.shared.u64 t, %1; cvt.u32.u64 %0, t; }" : "=r"(a) : "l"(p));
  return a;
}
__device__ __forceinline__ uint64_t ffma2(uint64_t a, uint64_t b, uint64_t c){
  uint64_t d; asm("fma.rn.f32x2 %0,%1,%2,%3;" : "=l"(d) : "l"(a),"l"(b),"l"(c)); return d;
}
__device__ __forceinline__ float sigm(float x){ return __fdividef(1.f, 1.f + __expf(-x)); }
__device__ __forceinline__ float tanh_(float x){ return 1.f - __fdividef(2.f, __expf(2.f*x)+1.f); }

#define MBAR_WAIT(addr, par)                                                   \
  {                                                                            \
    uint32_t done;                                                             \
    asm volatile(                                                              \
      "{\n\t.reg .pred p;\n\t"                                                 \
      "mbarrier.try_wait.parity.acquire.cta.shared::cta.b64 p, [%1], %2;\n\t"  \
      "selp.b32 %0, 1, 0, p;\n\t}"                                             \
      : "=r"(done) : "r"(addr), "r"(par) : "memory");                          \
    if (!done){                                                                \
      asm volatile(                                                            \
        "{\n\t.reg .pred P1;\n\tW_%=:\n\t"                                     \
        "mbarrier.try_wait.parity.acquire.cta.shared::cta.b64 P1, [%0], %1, 0x989680;\n\t" \
        "@P1 bra.uni D_%=;\n\tbra.uni W_%=;\n\tD_%=:\n\t}"                     \
        :: "r"(addr), "r"(par) : "memory");                                    \
    }                                                                          \
  }

// ---------------- Kernel A: X[dir] = emb@Wk_dir + b_dir ----------------
__global__ __launch_bounds__(608) void proj_kernel(
    const int* __restrict__ sentence,
    const float* __restrict__ E,
    const float* __restrict__ Wk_f, const float* __restrict__ b_f,
    const float* __restrict__ Wk_b, const float* __restrict__ b_b)
{
  int dir = blockIdx.y;
  const float* __restrict__ Wk = dir ? Wk_b : Wk_f;
  const float* __restrict__ bb = dir ? b_b : b_f;
  __shared__ __align__(16) float semb[TS*D_IN];
  __shared__ int srow[TS];
  int tid = threadIdx.x;
  int t0 = blockIdx.x * TS;
  if (tid < TS) srow[tid] = sentence[t0 + tid];
  __syncthreads();
  for (int e = tid; e < TS*D_IN; e += blockDim.x) {
    int s = e / D_IN, d = e - s*D_IN;
    semb[e] = E[(long)srow[s]*D_IN + d];
  }
  __syncthreads();
  if (tid >= ZDIM) return;
  int col = tid;
  float acc[TS];
  float bv = bb[col];
  #pragma unroll
  for (int s=0;s<TS;s++) acc[s]=bv;
  for (int k=0;k<D_IN;k+=4){
    float w0 = Wk[(k+0)*ZDIM+col];
    float w1 = Wk[(k+1)*ZDIM+col];
    float w2 = Wk[(k+2)*ZDIM+col];
    float w3 = Wk[(k+3)*ZDIM+col];
    #pragma unroll
    for (int s=0;s<TS;s++){
      float4 e4 = *reinterpret_cast<const float4*>(&semb[s*D_IN+k]);
      acc[s] += e4.x*w0 + e4.y*w1 + e4.z*w2 + e4.w*w3;
    }
  }
  #pragma unroll
  for (int s=0;s<TS;s++)
    g_X[dir][(long)(t0+s)*ZDIM + col] = acc[s];
}

// ---------------- LSTM: cluster of 2 CTAs per direction ----------------
// Thread c = 4u+g owns z-column G = g*150 + rank*75 + u. Recurrent weights
// split local-half/peer-half, 38 packed f32x2 each, in registers. Gates
// gathered via shfl into lane 4u (unit leader, holds c-state).
//
// Handoff protocol (arrival-count only — structurally no tx under/overflow):
//   mA (count=10): local h ready.  mB (count=10): peer h ready (peer arrives).
//   Leaders write h via plain st.shared (local) / st.shared::cluster (peer);
//   __syncwarp; lane0 of each warp posts arrive.release.cta on local mA and
//   arrive.release.cluster on the peer's mB. An arrive for phase ts is only
//   issued after that warp passed wait(ts-1), i.e. after the flip -> exactly
//   10 arrives per phase per barrier. Each warp's FMA reads precede its own
//   arrive, so double-buffer reuse is race-free.
struct LSmem3 {
  float hA[2][76];        // own units, double-buffered (75 + zero pad)
  float hB[2][76];        // peer units
  unsigned long long mbarA, mbarB;
};

__global__ void __cluster_dims__(2,1,1) __launch_bounds__(320,1)
lstm_kernel(const float* __restrict__ Wr_f, const float* __restrict__ Wr_b)
{
  __shared__ __align__(16) LSmem3 sm;
  int tid = threadIdx.x;
  int dir = blockIdx.x >> 1;
  uint32_t rank;
  asm("mov.u32 %0, %%cluster_ctarank;" : "=r"(rank));
  uint32_t peer = rank ^ 1u;
  const float* __restrict__ Wr = dir ? Wr_b : Wr_f;
  const float* __restrict__ X  = g_X[dir];

  int c = (tid < 300) ? tid : (tid - 20);   // clamp spare lanes (warp 9 tail)
  bool real = tid < 300;
  int u = c >> 2;                // unit within this CTA (0..74)
  int g = c & 3;                 // gate i,f,g,o
  int G = g*150 + (int)rank*75 + u;
  bool leader = real && (g == 0);

  // weights: half A = h indices [rank*75, +75), half B = peer's
  uint64_t wA[38], wB[38];
  {
    int baseA = (int)rank*75, baseB = (int)peer*75;
    #pragma unroll
    for (int m=0;m<38;m++){
      float a0 = (2*m   < 75) ? Wr[(baseA+2*m  )*ZDIM + G] : 0.f;
      float a1 = (2*m+1 < 75) ? Wr[(baseA+2*m+1)*ZDIM + G] : 0.f;
      float b0 = (2*m   < 75) ? Wr[(baseB+2*m  )*ZDIM + G] : 0.f;
      float b1 = (2*m+1 < 75) ? Wr[(baseB+2*m+1)*ZDIM + G] : 0.f;
      asm("mov.b64 %0,{%1,%2};" : "=l"(wA[m]) : "f"(a0), "f"(a1));
      asm("mov.b64 %0,{%1,%2};" : "=l"(wB[m]) : "f"(b0), "f"(b1));
    }
  }

  float* hraw = (float*)sm.hA;
  for (int i=tid;i<4*76;i+=320) hraw[i]=0.f;

  uint32_t s_hA = smem_u32(&sm.hA[0][0]);
  uint32_t s_hB = smem_u32(&sm.hB[0][0]);
  uint32_t s_mA = smem_u32(&sm.mbarA);
  uint32_t s_mB = smem_u32(&sm.mbarB);
  if (tid == 0){
    asm volatile("mbarrier.init.shared.b64 [%0], %1;" :: "r"(s_mA), "r"(10) : "memory");
    asm volatile("mbarrier.init.shared.b64 [%0], %1;" :: "r"(s_mB), "r"(10) : "memory");
  }
  __syncthreads();

  uint32_t r_hB, r_mB;
  asm("mapa.shared::cluster.u32 %0, %1, %2;" : "=r"(r_hB) : "r"(s_hB), "r"(peer));
  asm("mapa.shared::cluster.u32 %0, %1, %2;" : "=r"(r_mB) : "r"(s_mB), "r"(peer));

  // one-time cluster sync: peer smem (h zeros, mbars) initialized
  asm volatile("barrier.cluster.arrive.aligned;" ::: "memory");
  asm volatile("barrier.cluster.wait.aligned;"   ::: "memory");

  float creg = 0.f;
  float x = __ldg(&X[(dir ? (SEQ-1) : 0)*ZDIM + G]);

  for (int ts=0; ts<SEQ; ts++){
    int rb = ts & 1;
    uint32_t wpar = (uint32_t)((ts-1) & 1);   // parity of phase ts-1

    // ---- wait local half (fast path), FMA over hA ----
    if (ts > 0) MBAR_WAIT(s_mA, wpar);
    uint64_t a0=0ull, a1=0ull, a2=0ull, a3=0ull;
    {
      uint32_t ha = s_hA + rb*304;
      #pragma unroll
      for (int m=0;m<38;m+=2){
        uint64_t p0,p1;
        asm("ld.shared.v2.b64 {%0,%1},[%2];" : "=l"(p0),"=l"(p1) : "r"(ha + m*8));
        a0 = ffma2(p0, wA[m],   a0);
        a1 = ffma2(p1, wA[m+1], a1);
      }
    }
    // ---- wait peer half (flight hidden behind the FMA above), FMA over hB ----
    if (ts > 0) MBAR_WAIT(s_mB, wpar);
    {
      uint32_t hb = s_hB + rb*304;
      #pragma unroll
      for (int m=0;m<38;m+=2){
        uint64_t p0,p1;
        asm("ld.shared.v2.b64 {%0,%1},[%2];" : "=l"(p0),"=l"(p1) : "r"(hb + m*8));
        a2 = ffma2(p0, wB[m],   a2);
        a3 = ffma2(p1, wB[m+1], a3);
      }
    }
    float l0,h0,l1,h1,l2,h2,l3,h3;
    asm("mov.b64 {%0,%1},%2;" : "=f"(l0),"=f"(h0) : "l"(a0));
    asm("mov.b64 {%0,%1},%2;" : "=f"(l1),"=f"(h1) : "l"(a1));
    asm("mov.b64 {%0,%1},%2;" : "=f"(l2),"=f"(h2) : "l"(a2));
    asm("mov.b64 {%0,%1},%2;" : "=f"(l3),"=f"(h3) : "l"(a3));
    float z = x + ((l0+h0)+(l1+h1)) + ((l2+h2)+(l3+h3));

    // prefetch next step's x (L2 latency hidden behind gates + wait)
    if (ts+1 < SEQ){
      int tn = dir ? (SEQ-2-ts) : (ts+1);
      x = __ldg(&X[tn*ZDIM + G]);
    }

    // ---- gather the 4 gate pre-activations into the unit leader (lane 4u) ----
    float zf = __shfl_down_sync(0xFFFFFFFFu, z, 1);
    float zg = __shfl_down_sync(0xFFFFFFFFu, z, 2);
    float zo = __shfl_down_sync(0xFFFFFFFFu, z, 3);

    int wb = rb ^ 1;
    if (leader){
      float ig = sigm(z);
      float fg = sigm(zf);
      float gg = tanh_(zg);
      float og = sigm(zo);
      creg = fg*creg + ig*gg;
      float h = og*tanh_(creg);
      uint32_t off = (uint32_t)(wb*304 + u*4);
      sm.hA[wb][u] = h;                                  // local (plain STS)
      asm volatile("st.shared::cluster.f32 [%0], %1;"    // peer's hB
                   :: "r"(r_hB + off), "f"(h) : "memory");
      int t = dir ? (SEQ-1-ts) : ts;
      g_hidden[t*H1 + dir*UDIM + (int)rank*75 + u] = h;
    }
    __syncwarp();
    if ((tid & 31) == 0){
      // publish this warp's stores: local mA (cta release), peer mB (cluster release)
      asm volatile("mbarrier.arrive.release.cta.shared::cta.b64 _, [%0];"
                   :: "r"(s_mA) : "memory");
      asm volatile("mbarrier.arrive.release.cluster.shared::cluster.b64 _, [%0];"
                   :: "r"(r_mB) : "memory");
    }
  }

  // keep smem alive until all in-flight remote stores/arrives of both CTAs land
  asm volatile("barrier.cluster.arrive.aligned;" ::: "memory");
  asm volatile("barrier.cluster.wait.aligned;"   ::: "memory");
}

// ---------------- Kernel B: out = hidden@W1 + b1 ----------------
__global__ __launch_bounds__(320) void out_kernel(
    const float* __restrict__ W1, const float* __restrict__ b1)
{
  __shared__ __align__(16) float shid[TS*H1];
  int tid = threadIdx.x;
  int t0 = blockIdx.x * TS;
  for (int e=tid; e<TS*H1; e+=blockDim.x)
    shid[e] = g_hidden[(long)t0*H1 + e];
  __syncthreads();
  if (tid >= H1) return;
  int col = tid;
  float acc[TS];
  float bv = b1[col];
  #pragma unroll
  for (int s=0;s<TS;s++) acc[s]=bv;
  for (int k=0;k<H1;k+=4){
    float w0=W1[(k+0)*H1+col], w1=W1[(k+1)*H1+col];
    float w2=W1[(k+2)*H1+col], w3=W1[(k+3)*H1+col];
    #pragma unroll
    for (int s=0;s<TS;s++){
      float4 e4 = *reinterpret_cast<const float4*>(&shid[s*H1+k]);
      acc[s] += e4.x*w0+e4.y*w1+e4.z*w2+e4.w*w3;
    }
  }
  #pragma unroll
  for (int s=0;s<TS;s++) g_out[(long)(t0+s)*H1+col]=acc[s];
}

// ---------------- Kernel C: synonym attention per token ----------------
__global__ __launch_bounds__(128) void attn_kernel(
    const int* __restrict__ sentence,
    const int* __restrict__ syn_idx,
    const float* __restrict__ E,
    const float* __restrict__ W2, const float* __restrict__ b2)
{
  int s = blockIdx.x;
  int ids = (s==0)?0:(s-1);
  int tid = threadIdx.x;
  __shared__ float sout[H1], ssyn[NSYN*H1], shh[H1], red[128], scoef[NSYN], sc2;
  __shared__ int srow[NSYN];
  int token = sentence[s];
  if (tid < NSYN) srow[tid] = syn_idx[token*NSYN+tid];
  for (int d=tid; d<H1; d+=128) sout[d] = g_out[(long)ids*H1+d];
  __syncthreads();
  for (int e=tid; e<NSYN*H1; e+=128){
    int k=e/H1, d=e-k*H1;
    ssyn[e] = E[(long)srow[k]*D_IN + d];
  }
  __syncthreads();
  float p0=0,p1=0,p2=0,p3=0;
  for (int d=tid; d<H1; d+=128){
    float o = sout[d];
    p0 += ssyn[d]*o; p1 += ssyn[H1+d]*o; p2 += ssyn[2*H1+d]*o; p3 += ssyn[3*H1+d]*o;
  }
  float pv[4]={p0,p1,p2,p3};
  #pragma unroll
  for (int k=0;k<4;k++){
    red[tid]=pv[k]; __syncthreads();
    for (int off=64; off>0; off>>=1){
      if(tid<off) red[tid]+=red[tid+off];
      __syncthreads();
    }
    if (tid==0) scoef[k]=expf(red[0]);
    __syncthreads();
  }
  float q=0.f;
  for (int d=tid; d<H1; d+=128){
    float hh = scoef[0]*ssyn[d]+scoef[1]*ssyn[H1+d]
             + scoef[2]*ssyn[2*H1+d]+scoef[3]*ssyn[3*H1+d]
             + g_hidden[(long)ids*H1+d];
    shh[d]=hh;
    q += hh*W2[d];
  }
  red[tid]=q; __syncthreads();
  for (int off=64; off>0; off>>=1){
    if(tid<off) red[tid]+=red[tid+off];
    __syncthreads();
  }
  if (tid==0) sc2 = expf(tanhf(red[0]+b2[0]));
  __syncthreads();
  float c2v = sc2;
  for (int d=tid; d<H1; d+=128) g_wbuf[(long)s*H1+d] = c2v*shh[d];
}

// ---------------- Kernel D: H = sum_s wbuf[s]; logits ----------------
__global__ __launch_bounds__(320) void final_kernel(
    const float* __restrict__ We, const float* __restrict__ be,
    const float* __restrict__ Ws, const float* __restrict__ bs,
    float* __restrict__ dout)
{
  __shared__ float sH[H1];
  int tid = threadIdx.x;
  if (tid < H1){
    float a0=0,a1=0,a2=0,a3=0;
    for (int s=0;s<SEQ;s+=4){
      a0 += g_wbuf[(long)(s+0)*H1+tid];
      a1 += g_wbuf[(long)(s+1)*H1+tid];
      a2 += g_wbuf[(long)(s+2)*H1+tid];
      a3 += g_wbuf[(long)(s+3)*H1+tid];
    }
    sH[tid] = (a0+a1)+(a2+a3);
  }
  __syncthreads();
  if (tid < 9){
    float r = (tid<8)? be[tid] : bs[0];
    for (int d=0; d<H1; d++){
      float wv = (tid<8)? We[d*8+tid] : Ws[d];
      r += sH[d]*wv;
    }
    dout[tid] = r;
  }
}

// ---------------- launch ----------------
extern "C" void kernel_launch(void* const* d_in, const int* in_sizes, int n_in,
                              void* d_out, int out_size)
{
  const int*   sentence = (const int*)d_in[0];
  const int*   syn_idx  = (const int*)d_in[1];
  const float* E    = (const float*)d_in[2];
  const float* Wk_f = (const float*)d_in[3];
  const float* Wr_f = (const float*)d_in[4];
  const float* b_f  = (const float*)d_in[5];
  const float* Wk_b = (const float*)d_in[6];
  const float* Wr_b = (const float*)d_in[7];
  const float* b_b  = (const float*)d_in[8];
  const float* W1   = (const float*)d_in[9];
  const float* b1   = (const float*)d_in[10];
  const float* W2   = (const float*)d_in[11];
  const float* b2   = (const float*)d_in[12];
  const float* We   = (const float*)d_in[13];
  const float* be   = (const float*)d_in[14];
  const float* Ws   = (const float*)d_in[15];
  const float* bs   = (const float*)d_in[16];
  float* dout = (float*)d_out;

  dim3 gA(SEQ/TS, 2);
  proj_kernel<<<gA, 608>>>(sentence, E, Wk_f, b_f, Wk_b, b_b);
  lstm_kernel<<<4, 320>>>(Wr_f, Wr_b);           // 2 clusters of 2 (fwd, bwd)
  out_kernel<<<SEQ/TS, 320>>>(W1, b1);
  attn_kernel<<<SEQ, 128>>>(sentence, syn_idx, E, W2, b2);
  final_kernel<<<1, 320>>>(We, be, Ws, bs, dout);
}